// round 14
// baseline (speedup 1.0000x reference)
#include <cuda_runtime.h>
#include <cuda_fp16.h>

#define B_    2
#define S_    2048
#define H_    2048
#define NH    16
#define HD    128
#define BS    (B_ * S_)        // 4096 rows
#define QKV_N (3 * H_)         // 6144

// ---------------- scratch (device globals; no allocations allowed) ----------
__device__ double g_part1[512];
__device__ double g_part2[512];
__device__ float  g_scales[2];

__device__ __half g_wq[(size_t)QKV_N * H_];          // quantized qkv weight (fp16, exact ints)
__device__ __half g_wo[(size_t)H_ * H_];             // quantized o weight
__device__ __half g_xh[(size_t)BS * H_];             // x in fp16
__device__ __half g_qh[(size_t)B_ * NH * S_ * HD];   // [b,h,s,d], rope'd, pre-scaled by 1/sqrt(d)
__device__ __half g_kh[(size_t)B_ * NH * S_ * HD];   // [b,h,s,d], rope'd
__device__ __half g_vt[(size_t)B_ * NH * HD * S_];   // [b,h,d,s]  (V TRANSPOSED)
__device__ __half g_yh[(size_t)BS * H_];             // attention out, [b,s,h*d], fp16

// ---------------- cp.async helpers ------------------------------------------
__device__ __forceinline__ void cpa16(void* s, const void* g) {
    unsigned sa = (unsigned)__cvta_generic_to_shared(s);
    asm volatile("cp.async.cg.shared.global [%0], [%1], 16;\n" :: "r"(sa), "l"(g));
}
__device__ __forceinline__ void cpa_commit() { asm volatile("cp.async.commit_group;\n"); }
__device__ __forceinline__ void cpa_wait0()  { asm volatile("cp.async.wait_group 0;\n"); }
__device__ __forceinline__ void cpa_wait1()  { asm volatile("cp.async.wait_group 1;\n"); }
__device__ __forceinline__ void cpa_wait2()  { asm volatile("cp.async.wait_group 2;\n"); }

// ---------------- raw mma m16n8k16 (fp16 in, fp32 acc) ----------------------
__device__ __forceinline__ void mma16816(float* d, const unsigned* a, const unsigned* b,
                                         const float* c) {
    asm volatile(
        "mma.sync.aligned.m16n8k16.row.col.f32.f16.f16.f32 "
        "{%0,%1,%2,%3}, {%4,%5,%6,%7}, {%8,%9}, {%10,%11,%12,%13};\n"
        : "=f"(d[0]), "=f"(d[1]), "=f"(d[2]), "=f"(d[3])
        : "r"(a[0]), "r"(a[1]), "r"(a[2]), "r"(a[3]), "r"(b[0]), "r"(b[1]),
          "f"(c[0]), "f"(c[1]), "f"(c[2]), "f"(c[3]));
}

__device__ __forceinline__ void ldsm4(unsigned* r, unsigned addr) {
    asm volatile("ldmatrix.sync.aligned.m8n8.x4.shared.b16 {%0,%1,%2,%3}, [%4];"
        : "=r"(r[0]), "=r"(r[1]), "=r"(r[2]), "=r"(r[3]) : "r"(addr));
}

// ---------------- scale reduction (deterministic, double accum) -------------
__global__ void k_abs_partial(const float* __restrict__ Wq, const float* __restrict__ Wo) {
    __shared__ double ss[256];
    int which = blockIdx.y;
    size_t n4 = which ? ((size_t)H_ * H_ / 4) : ((size_t)QKV_N * H_ / 4);
    const float4* W4 = (const float4*)(which ? Wo : Wq);
    double acc = 0.0;
    for (size_t i = (size_t)blockIdx.x * blockDim.x + threadIdx.x; i < n4;
         i += (size_t)gridDim.x * blockDim.x) {
        float4 w = W4[i];
        acc += (double)(fabsf(w.x) + fabsf(w.y)) + (double)(fabsf(w.z) + fabsf(w.w));
    }
    ss[threadIdx.x] = acc;
    __syncthreads();
    for (int s = 128; s > 0; s >>= 1) {
        if (threadIdx.x < (unsigned)s) ss[threadIdx.x] += ss[threadIdx.x + s];
        __syncthreads();
    }
    if (threadIdx.x == 0) (which ? g_part2 : g_part1)[blockIdx.x] = ss[0];
}

__global__ void k_finalize_scales() {
    __shared__ double ss[256];
    int t = threadIdx.x;
    ss[t] = g_part1[t] + g_part1[t + 256];
    __syncthreads();
    for (int s = 128; s > 0; s >>= 1) {
        if (t < s) ss[t] += ss[t + s];
        __syncthreads();
    }
    if (t == 0) g_scales[0] = (float)(ss[0] / ((double)QKV_N * (double)H_));
    __syncthreads();
    ss[t] = g_part2[t] + g_part2[t + 256];
    __syncthreads();
    for (int s = 128; s > 0; s >>= 1) {
        if (t < s) ss[t] += ss[t + s];
        __syncthreads();
    }
    if (t == 0) g_scales[1] = (float)(ss[0] / ((double)H_ * (double)H_));
}

// ---------------- convert: quantize both weights + x->half in ONE launch ----
__global__ void k_convert(const float* __restrict__ Wq, const float* __restrict__ Wo,
                          const float* __restrict__ x) {
    int which = blockIdx.y;               // 0=wq, 1=wo, 2=x
    size_t n4;
    const float4* src;
    __half2* out;
    float inv;
    if (which == 0) {
        n4 = (size_t)QKV_N * H_ / 4; src = (const float4*)Wq; out = (__half2*)g_wq;
        inv = 1.0f / (g_scales[0] + 1e-5f);
    } else if (which == 1) {
        n4 = (size_t)H_ * H_ / 4; src = (const float4*)Wo; out = (__half2*)g_wo;
        inv = 1.0f / (g_scales[1] + 1e-5f);
    } else {
        n4 = (size_t)BS * H_ / 4; src = (const float4*)x; out = (__half2*)g_xh;
        inv = 0.0f;
    }
    if (which < 2) {
        for (size_t i = (size_t)blockIdx.x * blockDim.x + threadIdx.x; i < n4;
             i += (size_t)gridDim.x * blockDim.x) {
            float4 w = src[i];
            out[2 * i]     = __floats2half2_rn(rintf(w.x * inv), rintf(w.y * inv));
            out[2 * i + 1] = __floats2half2_rn(rintf(w.z * inv), rintf(w.w * inv));
        }
    } else {
        for (size_t i = (size_t)blockIdx.x * blockDim.x + threadIdx.x; i < n4;
             i += (size_t)gridDim.x * blockDim.x) {
            float4 w = src[i];
            out[2 * i]     = __floats2half2_rn(w.x, w.y);
            out[2 * i + 1] = __floats2half2_rn(w.z, w.w);
        }
    }
}

// ---------------- 3-stage pipelined RAW-MMA GEMM, K-step 64 -----------------
// 8 warps, 32x64 per warp, ldmatrix.x4 operands, software-pipelined fragments.
// C[M,N] = A[M,K] * B[N,K]^T * scale
// which==0: A=g_xh, B=g_wq, fused RoPE epilogue -> g_qh/g_kh/g_vt (fp16)
// which==1: A=g_yh, B=g_wo, direct fp32 store -> Cout
#define GLD   72                              // 64 + 8 pad (halfs)
#define GSTG  (128 * GLD)                     // halfs per tile per stage
#define GSM_PIPE  (3 * 2 * GSTG * 2)          // 110592 B
#define GSM_TOTAL GSM_PIPE                    // scratch (67584) aliases, smaller

__global__ __launch_bounds__(256, 2) void k_gemm(float* __restrict__ Cout,
                                                 const float* __restrict__ rot,
                                                 int M, int N, int K, int which) {
    extern __shared__ char gsm[];
    __half* sA = (__half*)gsm;                 // [3][128][GLD]
    __half* sB = sA + 3 * GSTG;                // [3][128][GLD]
    float*  sc = (float*)gsm;                  // [128][132] epilogue scratch (aliases)

    const __half* A = which ? g_yh : g_xh;
    const __half* B = which ? g_wo : g_wq;

    int bm = blockIdx.y * 128, bn = blockIdx.x * 128;
    int tid = threadIdx.x, warp = tid >> 5, lane = tid & 31;
    int wm = (warp & 3) * 32, wn = (warp >> 2) * 64;
    int l4 = lane >> 2, lq = lane & 3;

    // ldmatrix per-lane byte offsets within a stage tile
    int lrow = lane & 15, lcol8 = (lane >> 4) << 3;
    unsigned aoff = (unsigned)(((wm + lrow) * GLD + lcol8) * 2);
    unsigned boff = (unsigned)(((wn + lrow) * GLD + lcol8) * 2);
    unsigned sAb = (unsigned)__cvta_generic_to_shared(sA);
    unsigned sBb = (unsigned)__cvta_generic_to_shared(sB);

    float acc[2][8][4];
#pragma unroll
    for (int i = 0; i < 2; i++)
#pragma unroll
        for (int j = 0; j < 8; j++)
#pragma unroll
            for (int e = 0; e < 4; e++) acc[i][j][e] = 0.0f;

    auto issue = [&](int kt, int buf) {
        int k0 = kt * 64;
        __half* dA = sA + buf * GSTG;
        __half* dB = sB + buf * GSTG;
#pragma unroll
        for (int i = 0; i < 4; i++) {          // 1024 uint4 chunks per tile
            int ch = tid + i * 256;
            int r = ch >> 3, c = (ch & 7) << 3;
            cpa16(dA + r * GLD + c, A + (size_t)(bm + r) * K + k0 + c);
            cpa16(dB + r * GLD + c, B + (size_t)(bn + r) * K + k0 + c);
        }
        cpa_commit();
    };

    int KT = K >> 6;                           // 32 for K=2048
    issue(0, 0);
    issue(1, 1);
    for (int kt = 0; kt < KT; kt++) {
        int buf = kt % 3;
        if (kt + 1 < KT) cpa_wait1();          // group kt retired
        else             cpa_wait0();
        __syncthreads();                       // stage kt visible; stage (kt+2)%3 free
        if (kt + 2 < KT) issue(kt + 2, (kt + 2) % 3);

        unsigned pAa = sAb + (unsigned)(buf * GSTG * 2) + aoff;
        unsigned pBa = sBb + (unsigned)(buf * GSTG * 2) + boff;

        unsigned a[2][4], b[4][4];
        // preload kk=0 fragments
        ldsm4(a[0], pAa);
        ldsm4(a[1], pAa + 16 * GLD * 2);
#pragma unroll
        for (int nt = 0; nt < 4; nt++) ldsm4(b[nt], pBa + nt * 16 * GLD * 2);

#pragma unroll
        for (int kk = 0; kk < 4; kk++) {
            unsigned an[2][4], bnf[4][4];
            if (kk < 3) {                       // prefetch kk+1
                unsigned ka = pAa + (kk + 1) * 32;       // 16 halfs = 32 B
                unsigned kb = pBa + (kk + 1) * 32;
                ldsm4(an[0], ka);
                ldsm4(an[1], ka + 16 * GLD * 2);
#pragma unroll
                for (int nt = 0; nt < 4; nt++) ldsm4(bnf[nt], kb + nt * 16 * GLD * 2);
            }
#pragma unroll
            for (int nt = 0; nt < 4; nt++) {
                unsigned bf0[2] = {b[nt][0], b[nt][2]};
                unsigned bf1[2] = {b[nt][1], b[nt][3]};
                mma16816(acc[0][2 * nt],     a[0], bf0, acc[0][2 * nt]);
                mma16816(acc[0][2 * nt + 1], a[0], bf1, acc[0][2 * nt + 1]);
                mma16816(acc[1][2 * nt],     a[1], bf0, acc[1][2 * nt]);
                mma16816(acc[1][2 * nt + 1], a[1], bf1, acc[1][2 * nt + 1]);
            }
            if (kk < 3) {
#pragma unroll
                for (int e = 0; e < 4; e++) {
                    a[0][e] = an[0][e];
                    a[1][e] = an[1][e];
#pragma unroll
                    for (int nt = 0; nt < 4; nt++) b[nt][e] = bnf[nt][e];
                }
            }
        }
    }
    __syncthreads();                           // all compute done before scratch alias

    float s = g_scales[which];

    if (which == 1) {
        // direct fp32 store (raw fragment layout: rows l4/l4+8, cols n8*8+2lq)
#pragma unroll
        for (int mt = 0; mt < 2; mt++) {
#pragma unroll
            for (int n8 = 0; n8 < 8; n8++) {
                float* base = Cout + (size_t)(bm + wm + mt * 16 + l4) * N
                              + bn + wn + n8 * 8 + 2 * lq;
                float2 v0 = {acc[mt][n8][0] * s, acc[mt][n8][1] * s};
                float2 v1 = {acc[mt][n8][2] * s, acc[mt][n8][3] * s};
                *(float2*)base = v0;
                *(float2*)(base + 8 * N) = v1;
            }
        }
        return;
    }

    // which==0: stage through scratch, fused RoPE + transpose + fp16 epilogue
#pragma unroll
    for (int mt = 0; mt < 2; mt++) {
#pragma unroll
        for (int n8 = 0; n8 < 8; n8++) {
            float* base = sc + (wm + mt * 16 + l4) * 132 + wn + n8 * 8 + 2 * lq;
            float2 v0 = {acc[mt][n8][0] * s, acc[mt][n8][1] * s};
            float2 v1 = {acc[mt][n8][2] * s, acc[mt][n8][3] * s};
            *(float2*)base = v0;
            *(float2*)(base + 8 * 132) = v1;
        }
    }
    __syncthreads();

    int sel = bn >> 11;                 // 0=q, 1=k, 2=v
    int h = (bn & 2047) >> 7;           // head index
    if (sel == 2) {
        // V: write TRANSPOSED [b,h,d,s]
        int b = bm >> 11;
        int s0 = bm & 2047;
        size_t vtbase = ((size_t)(b * NH + h)) * HD * S_;
        for (int idx = tid; idx < 128 * 128; idx += 256) {
            int d = idx >> 7, sl = idx & 127;          // output row=d, col=s
            float v = sc[sl * 132 + d];
            g_vt[vtbase + (size_t)d * S_ + s0 + sl] = __float2half(v);
        }
        return;
    }
    for (int idx = tid; idx < 128 * 128; idx += 256) {
        int r = idx >> 7, c = idx & 127;
        int row = bm + r;
        int b = row >> 11, sPos = row & 2047;
        float v = sc[r * 132 + c];
        size_t ob = ((size_t)((b * NH + h) * S_ + sPos)) * HD + c;
        float vr = (c < 64) ? -sc[r * 132 + c + 64] : sc[r * 132 + c - 64];
        float sinv = rot[sPos * HD + c];
        float cosv = rot[S_ * HD + sPos * HD + c];
        float o = v * cosv + vr * sinv;
        if (sel == 0) g_qh[ob] = __float2half(o * 0.08838834764831845f);
        else          g_kh[ob] = __float2half(o);
    }
}

// ---------------- Flash attention v2 (causal), 3-stage KV, 1 barrier/iter ---
// CTA: 128 q-rows, 8 warps x 16 rows.  KV tiles: 64 wide, TRIPLE buffered.
#define QLD 136
#define KLD 136
#define VLD 72
#define KSTG (64 * KLD)                          // halfs per K stage
#define VSTG (128 * VLD)                         // halfs per Vt stage
#define FA2_SQ   (128 * QLD * 2)                 // 34816
#define FA2_SMEM (FA2_SQ + 3 * (KSTG + VSTG) * 2)  // 142336

__global__ __launch_bounds__(256, 1) void k_flash2() {
    extern __shared__ char smem[];
    __half* sQ = (__half*)smem;
    __half* sK = sQ + 128 * QLD;                 // [3][64][KLD]
    __half* sVt = sK + 3 * KSTG;                 // [3][128][VLD]

    const int qtb = blockIdx.x, h = blockIdx.y, b = blockIdx.z;
    const int q0 = qtb * 128;
    const int tid = threadIdx.x, warp = tid >> 5, lane = tid & 31;
    const int l4 = lane >> 2, lq = lane & 3;
    const int wr = warp * 16;                      // warp's local q-row base
    const size_t headQK = ((size_t)(b * NH + h)) * S_ * HD;
    const size_t headVt = ((size_t)(b * NH + h)) * HD * S_;
    const float NEG_INF = __int_as_float(0xff800000);

    const int ktmax = 2 * qtb + 1;                 // inclusive

    auto issueKV = [&](int kt, int buf) {
        const int k0 = kt * 64;
        __half* dK = sK + buf * KSTG;
        __half* dV = sVt + buf * VSTG;
#pragma unroll
        for (int i = 0; i < 4; i++) {              // K: 64 rows x 16 chunks
            int ch = tid + i * 256;
            int r = ch >> 4, c = (ch & 15) << 3;
            cpa16(dK + r * KLD + c, g_kh + headQK + (size_t)(k0 + r) * HD + c);
        }
#pragma unroll
        for (int i = 0; i < 4; i++) {              // Vt: 128 rows x 8 chunks
            int ch = tid + i * 256;
            int r = ch >> 3, c = (ch & 7) << 3;
            cpa16(dV + r * VLD + c, g_vt + headVt + (size_t)r * S_ + k0 + c);
        }
        cpa_commit();
    };

    // prologue: Q group, then KV(0), KV(1)
#pragma unroll
    for (int i = 0; i < 8; i++) {                  // Q: 128 rows x 16 chunks
        int ch = tid + i * 256;
        int r = ch >> 4, c = (ch & 15) << 3;
        cpa16(sQ + r * QLD + c, g_qh + headQK + (size_t)(q0 + r) * HD + c);
    }
    cpa_commit();
    issueKV(0, 0);
    issueKV(1, 1);                                 // ktmax >= 1 always
    cpa_wait2();                                   // Q retired (KV0,KV1 may pend)
    __syncthreads();

    // preload Q A-fragments: 8 k-blocks x 4 regs
    unsigned qa[8][4];
    {
        const __half* q0p = sQ + (wr + l4) * QLD;
        const __half* q1p = q0p + 8 * QLD;
#pragma unroll
        for (int kb = 0; kb < 8; kb++) {
            qa[kb][0] = *(const unsigned*)&q0p[kb * 16 + 2 * lq];
            qa[kb][1] = *(const unsigned*)&q1p[kb * 16 + 2 * lq];
            qa[kb][2] = *(const unsigned*)&q0p[kb * 16 + 2 * lq + 8];
            qa[kb][3] = *(const unsigned*)&q1p[kb * 16 + 2 * lq + 8];
        }
    }

    float oacc[16][4];
#pragma unroll
    for (int t = 0; t < 16; t++)
#pragma unroll
        for (int e = 0; e < 4; e++) oacc[t][e] = 0.0f;
    float m0 = -1e30f, m1 = -1e30f, l0 = 0.0f, l1 = 0.0f;

    const int qrow0 = q0 + wr + l4;                // global rows of this thread
    const int qrow1 = qrow0 + 8;

    for (int kt = 0; kt <= ktmax; kt++) {
        const int cur = kt % 3;
        const int k0 = kt * 64;
        if (kt + 1 <= ktmax) cpa_wait1();          // KV(kt) retired; KV(kt+1) pends
        else                 cpa_wait0();
        __syncthreads();                           // KV(kt) visible; stage (kt+2)%3 free
        if (kt + 2 <= ktmax) issueKV(kt + 2, (kt + 2) % 3);

        const bool active = (k0 <= q0 + wr + 15);
        if (active) {
            const __half* pK = sK + cur * KSTG;
            const __half* pVt = sVt + cur * VSTG;

            // ---- S = Q K^T : 8 n-tiles (8 kv each) ----
            float sacc[8][4];
#pragma unroll
            for (int n = 0; n < 8; n++) {
#pragma unroll
                for (int e = 0; e < 4; e++) sacc[n][e] = 0.0f;
                const __half* kp = pK + (n * 8 + l4) * KLD;
#pragma unroll
                for (int kb = 0; kb < 8; kb++) {
                    unsigned bb[2];
                    bb[0] = *(const unsigned*)&kp[kb * 16 + 2 * lq];
                    bb[1] = *(const unsigned*)&kp[kb * 16 + 2 * lq + 8];
                    mma16816(sacc[n], qa[kb], bb, sacc[n]);
                }
            }

            // ---- causal mask ----
            if (k0 + 63 > q0 + wr) {
#pragma unroll
                for (int n = 0; n < 8; n++) {
                    int c0 = k0 + n * 8 + 2 * lq;
                    if (c0 > qrow0)     sacc[n][0] = NEG_INF;
                    if (c0 + 1 > qrow0) sacc[n][1] = NEG_INF;
                    if (c0 > qrow1)     sacc[n][2] = NEG_INF;
                    if (c0 + 1 > qrow1) sacc[n][3] = NEG_INF;
                }
            }

            // ---- online softmax in registers ----
            float mx0 = NEG_INF, mx1 = NEG_INF;
#pragma unroll
            for (int n = 0; n < 8; n++) {
                mx0 = fmaxf(mx0, fmaxf(sacc[n][0], sacc[n][1]));
                mx1 = fmaxf(mx1, fmaxf(sacc[n][2], sacc[n][3]));
            }
            mx0 = fmaxf(mx0, __shfl_xor_sync(0xffffffffu, mx0, 1));
            mx0 = fmaxf(mx0, __shfl_xor_sync(0xffffffffu, mx0, 2));
            mx1 = fmaxf(mx1, __shfl_xor_sync(0xffffffffu, mx1, 1));
            mx1 = fmaxf(mx1, __shfl_xor_sync(0xffffffffu, mx1, 2));
            float m0n = fmaxf(m0, mx0);
            float m1n = fmaxf(m1, mx1);
            float sum0 = 0.f, sum1 = 0.f;
#pragma unroll
            for (int n = 0; n < 8; n++) {
                sacc[n][0] = __expf(sacc[n][0] - m0n);
                sacc[n][1] = __expf(sacc[n][1] - m0n);
                sacc[n][2] = __expf(sacc[n][2] - m1n);
                sacc[n][3] = __expf(sacc[n][3] - m1n);
                sum0 += sacc[n][0] + sacc[n][1];
                sum1 += sacc[n][2] + sacc[n][3];
            }
            sum0 += __shfl_xor_sync(0xffffffffu, sum0, 1);
            sum0 += __shfl_xor_sync(0xffffffffu, sum0, 2);
            sum1 += __shfl_xor_sync(0xffffffffu, sum1, 1);
            sum1 += __shfl_xor_sync(0xffffffffu, sum1, 2);
            float al0 = __expf(m0 - m0n);
            float al1 = __expf(m1 - m1n);
            m0 = m0n; m1 = m1n;
            l0 = l0 * al0 + sum0;
            l1 = l1 * al1 + sum1;

            // ---- pack P (fp16 A-fragments) ----
            unsigned pa[4][4];
#pragma unroll
            for (int j = 0; j < 4; j++) {
                __half2 h0 = __floats2half2_rn(sacc[2 * j][0], sacc[2 * j][1]);
                __half2 h1 = __floats2half2_rn(sacc[2 * j][2], sacc[2 * j][3]);
                __half2 h2 = __floats2half2_rn(sacc[2 * j + 1][0], sacc[2 * j + 1][1]);
                __half2 h3 = __floats2half2_rn(sacc[2 * j + 1][2], sacc[2 * j + 1][3]);
                pa[j][0] = *(unsigned*)&h0;
                pa[j][1] = *(unsigned*)&h1;
                pa[j][2] = *(unsigned*)&h2;
                pa[j][3] = *(unsigned*)&h3;
            }

            // ---- rescale O, then O += P * Vt ----
#pragma unroll
            for (int t = 0; t < 16; t++) {
                oacc[t][0] *= al0; oacc[t][1] *= al0;
                oacc[t][2] *= al1; oacc[t][3] *= al1;
            }
#pragma unroll
            for (int t = 0; t < 16; t++) {
                const __half* vp = pVt + (t * 8 + l4) * VLD;
#pragma unroll
                for (int j = 0; j < 4; j++) {
                    unsigned bb[2];
                    bb[0] = *(const unsigned*)&vp[j * 16 + 2 * lq];
                    bb[1] = *(const unsigned*)&vp[j * 16 + 2 * lq + 8];
                    mma16816(oacc[t], pa[j], bb, oacc[t]);
                }
            }
        }
    }

    // ---- epilogue: O / l -> stage in sQ (half) -> coalesced store ----
    __syncthreads();                               // last KV reads done; sQ reusable
    {
        float inv0 = 1.0f / l0, inv1 = 1.0f / l1;
        __half* st0 = sQ + (wr + l4) * QLD;
        __half* st1 = st0 + 8 * QLD;
#pragma unroll
        for (int t = 0; t < 16; t++) {
            __half2 h0 = __floats2half2_rn(oacc[t][0] * inv0, oacc[t][1] * inv0);
            __half2 h1 = __floats2half2_rn(oacc[t][2] * inv1, oacc[t][3] * inv1);
            *(__half2*)&st0[t * 8 + 2 * lq] = h0;
            *(__half2*)&st1[t * 8 + 2 * lq] = h1;
        }
    }
    __syncthreads();
#pragma unroll
    for (int i = 0; i < 8; i++) {
        int ch = tid + i * 256;
        int r = ch >> 4, c = (ch & 15) << 3;
        *(uint4*)&g_yh[((size_t)(b * S_ + q0 + r)) * H_ + h * HD + c] =
            *(const uint4*)&sQ[r * QLD + c];
    }
}

// ---------------- launch -----------------------------------------------------
extern "C" void kernel_launch(void* const* d_in, const int* in_sizes, int n_in,
                              void* d_out, int out_size) {
    (void)in_sizes; (void)n_in; (void)out_size;
    const float* x      = (const float*)d_in[0];
    const float* rotary = (const float*)d_in[1];
    const float* qkvw   = (const float*)d_in[2];
    const float* ow     = (const float*)d_in[3];
    float* out = (float*)d_out;

    static int attr_set = 0;
    if (!attr_set) {
        cudaFuncSetAttribute(k_gemm, cudaFuncAttributeMaxDynamicSharedMemorySize, GSM_TOTAL);
        cudaFuncSetAttribute(k_flash2, cudaFuncAttributeMaxDynamicSharedMemorySize, FA2_SMEM);
        attr_set = 1;
    }

    // 1) deterministic scales (both weights in one launch)
    k_abs_partial<<<dim3(512, 2), 256>>>(qkvw, ow);
    k_finalize_scales<<<1, 256>>>();

    // 2) quantize both weights + x->half in ONE launch
    k_convert<<<dim3(1024, 3), 256>>>(qkvw, ow, x);

    // 3) QKV projection + fused RoPE/transpose epilogue (V transposed)
    k_gemm<<<dim3(QKV_N / 128, BS / 128), 256, GSM_TOTAL>>>(nullptr, rotary, BS, QKV_N, H_, 0);

    // 4) flash attention v2 (causal, register-resident, 3-stage KV)
    k_flash2<<<dim3(S_ / 128, NH, B_), 256, FA2_SMEM>>>();

    // 5) output projection -> d_out (fp32)
    k_gemm<<<dim3(H_ / 128, BS / 128), 256, GSM_TOTAL>>>(out, nullptr, BS, H_, H_, 1);
}

// round 15
// speedup vs baseline: 1.0892x; 1.0892x over previous
#include <cuda_runtime.h>
#include <cuda_fp16.h>
#include <mma.h>

using namespace nvcuda;

#define B_    2
#define S_    2048
#define H_    2048
#define NH    16
#define HD    128
#define BS    (B_ * S_)        // 4096 rows
#define QKV_N (3 * H_)         // 6144

// ---------------- scratch (device globals; no allocations allowed) ----------
__device__ double g_part1[512];
__device__ double g_part2[512];
__device__ float  g_scales[2];

__device__ __half g_wq[(size_t)QKV_N * H_];          // quantized qkv weight (fp16, exact ints)
__device__ __half g_wo[(size_t)H_ * H_];             // quantized o weight
__device__ __half g_xh[(size_t)BS * H_];             // x in fp16
__device__ __half g_qh[(size_t)B_ * NH * S_ * HD];   // [b,h,s,d], rope'd, pre-scaled by 1/sqrt(d)
__device__ __half g_kh[(size_t)B_ * NH * S_ * HD];   // [b,h,s,d], rope'd
__device__ __half g_vt[(size_t)B_ * NH * HD * S_];   // [b,h,d,s]  (V TRANSPOSED)
__device__ __half g_yh[(size_t)BS * H_];             // attention out, [b,s,h*d], fp16

// ---------------- cp.async helpers ------------------------------------------
__device__ __forceinline__ void cpa16(void* s, const void* g) {
    unsigned sa = (unsigned)__cvta_generic_to_shared(s);
    asm volatile("cp.async.cg.shared.global [%0], [%1], 16;\n" :: "r"(sa), "l"(g));
}
__device__ __forceinline__ void cpa_commit() { asm volatile("cp.async.commit_group;\n"); }
__device__ __forceinline__ void cpa_wait0()  { asm volatile("cp.async.wait_group 0;\n"); }
__device__ __forceinline__ void cpa_wait1()  { asm volatile("cp.async.wait_group 1;\n"); }
__device__ __forceinline__ void cpa_wait2()  { asm volatile("cp.async.wait_group 2;\n"); }

// ---------------- raw mma m16n8k16 (fp16 in, fp32 acc) ----------------------
__device__ __forceinline__ void mma16816(float* d, const unsigned* a, const unsigned* b,
                                         const float* c) {
    asm volatile(
        "mma.sync.aligned.m16n8k16.row.col.f32.f16.f16.f32 "
        "{%0,%1,%2,%3}, {%4,%5,%6,%7}, {%8,%9}, {%10,%11,%12,%13};\n"
        : "=f"(d[0]), "=f"(d[1]), "=f"(d[2]), "=f"(d[3])
        : "r"(a[0]), "r"(a[1]), "r"(a[2]), "r"(a[3]), "r"(b[0]), "r"(b[1]),
          "f"(c[0]), "f"(c[1]), "f"(c[2]), "f"(c[3]));
}

// ---------------- scale reduction (deterministic, double accum) -------------
__global__ void k_abs_partial(const float* __restrict__ Wq, const float* __restrict__ Wo) {
    __shared__ double ss[256];
    int which = blockIdx.y;
    size_t n4 = which ? ((size_t)H_ * H_ / 4) : ((size_t)QKV_N * H_ / 4);
    const float4* W4 = (const float4*)(which ? Wo : Wq);
    double acc = 0.0;
    for (size_t i = (size_t)blockIdx.x * blockDim.x + threadIdx.x; i < n4;
         i += (size_t)gridDim.x * blockDim.x) {
        float4 w = W4[i];
        acc += (double)(fabsf(w.x) + fabsf(w.y)) + (double)(fabsf(w.z) + fabsf(w.w));
    }
    ss[threadIdx.x] = acc;
    __syncthreads();
    for (int s = 128; s > 0; s >>= 1) {
        if (threadIdx.x < (unsigned)s) ss[threadIdx.x] += ss[threadIdx.x + s];
        __syncthreads();
    }
    if (threadIdx.x == 0) (which ? g_part2 : g_part1)[blockIdx.x] = ss[0];
}

__global__ void k_finalize_scales() {
    __shared__ double ss[256];
    int t = threadIdx.x;
    ss[t] = g_part1[t] + g_part1[t + 256];
    __syncthreads();
    for (int s = 128; s > 0; s >>= 1) {
        if (t < s) ss[t] += ss[t + s];
        __syncthreads();
    }
    if (t == 0) g_scales[0] = (float)(ss[0] / ((double)QKV_N * (double)H_));
    __syncthreads();
    ss[t] = g_part2[t] + g_part2[t + 256];
    __syncthreads();
    for (int s = 128; s > 0; s >>= 1) {
        if (t < s) ss[t] += ss[t + s];
        __syncthreads();
    }
    if (t == 0) g_scales[1] = (float)(ss[0] / ((double)H_ * (double)H_));
}

// ---------------- convert: quantize both weights + x->half in ONE launch ----
__global__ void k_convert(const float* __restrict__ Wq, const float* __restrict__ Wo,
                          const float* __restrict__ x) {
    int which = blockIdx.y;               // 0=wq, 1=wo, 2=x
    size_t n4;
    const float4* src;
    __half2* out;
    float inv;
    if (which == 0) {
        n4 = (size_t)QKV_N * H_ / 4; src = (const float4*)Wq; out = (__half2*)g_wq;
        inv = 1.0f / (g_scales[0] + 1e-5f);
    } else if (which == 1) {
        n4 = (size_t)H_ * H_ / 4; src = (const float4*)Wo; out = (__half2*)g_wo;
        inv = 1.0f / (g_scales[1] + 1e-5f);
    } else {
        n4 = (size_t)BS * H_ / 4; src = (const float4*)x; out = (__half2*)g_xh;
        inv = 0.0f;
    }
    if (which < 2) {
        for (size_t i = (size_t)blockIdx.x * blockDim.x + threadIdx.x; i < n4;
             i += (size_t)gridDim.x * blockDim.x) {
            float4 w = src[i];
            out[2 * i]     = __floats2half2_rn(rintf(w.x * inv), rintf(w.y * inv));
            out[2 * i + 1] = __floats2half2_rn(rintf(w.z * inv), rintf(w.w * inv));
        }
    } else {
        for (size_t i = (size_t)blockIdx.x * blockDim.x + threadIdx.x; i < n4;
             i += (size_t)gridDim.x * blockDim.x) {
            float4 w = src[i];
            out[2 * i]     = __floats2half2_rn(w.x, w.y);
            out[2 * i + 1] = __floats2half2_rn(w.z, w.w);
        }
    }
}

// ---------------- 3-stage pipelined WMMA GEMM, K-step 64, 1 barrier/step ----
// (R13 configuration: 8 warps, 32x64 per warp, launch_bounds(256,2))
// C[M,N] = A[M,K] * B[N,K]^T * scale
// which==0: A=g_xh, B=g_wq, fused RoPE epilogue -> g_qh/g_kh/g_vt (fp16)
// which==1: A=g_yh, B=g_wo, direct fp32 store -> Cout
#define GLD   72                              // 64 + 8 pad (halfs)
#define GSTG  (128 * GLD)                     // halfs per tile per stage
#define GSM_PIPE  (3 * 2 * GSTG * 2)          // 110592 B
#define GSM_TOTAL GSM_PIPE                    // scratch (67584) aliases, smaller

__global__ __launch_bounds__(256, 2) void k_gemm(float* __restrict__ Cout,
                                                 const float* __restrict__ rot,
                                                 int M, int N, int K, int which) {
    extern __shared__ char gsm[];
    __half* sA = (__half*)gsm;                 // [3][128][GLD]
    __half* sB = sA + 3 * GSTG;                // [3][128][GLD]
    float*  sc = (float*)gsm;                  // [128][132] epilogue scratch (aliases)

    const __half* A = which ? g_yh : g_xh;
    const __half* B = which ? g_wo : g_wq;

    int bm = blockIdx.y * 128, bn = blockIdx.x * 128;
    int tid = threadIdx.x, warp = tid >> 5;
    int wm = (warp & 3) * 32, wn = (warp >> 2) * 64;

    wmma::fragment<wmma::accumulator, 16, 16, 16, float> acc[2][4];
#pragma unroll
    for (int i = 0; i < 2; i++)
#pragma unroll
        for (int j = 0; j < 4; j++) wmma::fill_fragment(acc[i][j], 0.0f);

    auto issue = [&](int kt, int buf) {
        int k0 = kt * 64;
        __half* dA = sA + buf * GSTG;
        __half* dB = sB + buf * GSTG;
#pragma unroll
        for (int i = 0; i < 4; i++) {          // 1024 uint4 chunks per tile
            int ch = tid + i * 256;
            int r = ch >> 3, c = (ch & 7) << 3;
            cpa16(dA + r * GLD + c, A + (size_t)(bm + r) * K + k0 + c);
            cpa16(dB + r * GLD + c, B + (size_t)(bn + r) * K + k0 + c);
        }
        cpa_commit();
    };

    int KT = K >> 6;                           // 32 for K=2048
    issue(0, 0);
    issue(1, 1);
    for (int kt = 0; kt < KT; kt++) {
        int buf = kt % 3;
        if (kt + 1 < KT) cpa_wait1();          // group kt retired
        else             cpa_wait0();
        __syncthreads();                       // stage kt visible; stage (kt+2)%3 free
        if (kt + 2 < KT) issue(kt + 2, (kt + 2) % 3);
        const __half* pA = sA + buf * GSTG;
        const __half* pB = sB + buf * GSTG;
#pragma unroll
        for (int kk = 0; kk < 64; kk += 16) {
            wmma::fragment<wmma::matrix_a, 16, 16, 16, __half, wmma::row_major> af[2];
            wmma::load_matrix_sync(af[0], pA + wm * GLD + kk, GLD);
            wmma::load_matrix_sync(af[1], pA + (wm + 16) * GLD + kk, GLD);
#pragma unroll
            for (int j = 0; j < 4; j++) {
                wmma::fragment<wmma::matrix_b, 16, 16, 16, __half, wmma::col_major> bf;
                wmma::load_matrix_sync(bf, pB + (wn + j * 16) * GLD + kk, GLD);
                wmma::mma_sync(acc[0][j], af[0], bf, acc[0][j]);
                wmma::mma_sync(acc[1][j], af[1], bf, acc[1][j]);
            }
        }
    }
    __syncthreads();                           // all compute done before scratch alias

    float s = g_scales[which];
#pragma unroll
    for (int i = 0; i < 2; i++)
#pragma unroll
        for (int j = 0; j < 4; j++)
            for (int e = 0; e < acc[i][j].num_elements; e++) acc[i][j].x[e] *= s;

    if (which == 1) {
        // direct fp32 store
#pragma unroll
        for (int i = 0; i < 2; i++)
#pragma unroll
            for (int j = 0; j < 4; j++)
                wmma::store_matrix_sync(Cout + (size_t)(bm + wm + i * 16) * N + bn + wn + j * 16,
                                        acc[i][j], N, wmma::mem_row_major);
        return;
    }

    // which==0: stage through scratch, fused RoPE + transpose + fp16 epilogue
#pragma unroll
    for (int i = 0; i < 2; i++)
#pragma unroll
        for (int j = 0; j < 4; j++)
            wmma::store_matrix_sync(sc + (wm + i * 16) * 132 + wn + j * 16,
                                    acc[i][j], 132, wmma::mem_row_major);
    __syncthreads();

    int sel = bn >> 11;                 // 0=q, 1=k, 2=v
    int h = (bn & 2047) >> 7;           // head index
    if (sel == 2) {
        // V: write TRANSPOSED [b,h,d,s]
        int b = bm >> 11;
        int s0 = bm & 2047;
        size_t vtbase = ((size_t)(b * NH + h)) * HD * S_;
        for (int idx = tid; idx < 128 * 128; idx += 256) {
            int d = idx >> 7, sl = idx & 127;          // output row=d, col=s
            float v = sc[sl * 132 + d];
            g_vt[vtbase + (size_t)d * S_ + s0 + sl] = __float2half(v);
        }
        return;
    }
    for (int idx = tid; idx < 128 * 128; idx += 256) {
        int r = idx >> 7, c = idx & 127;
        int row = bm + r;
        int b = row >> 11, sPos = row & 2047;
        float v = sc[r * 132 + c];
        size_t ob = ((size_t)((b * NH + h) * S_ + sPos)) * HD + c;
        float vr = (c < 64) ? -sc[r * 132 + c + 64] : sc[r * 132 + c - 64];
        float sinv = rot[sPos * HD + c];
        float cosv = rot[S_ * HD + sPos * HD + c];
        float o = v * cosv + vr * sinv;
        if (sel == 0) g_qh[ob] = __float2half(o * 0.08838834764831845f);
        else          g_kh[ob] = __float2half(o);
    }
}

// ---------------- Flash attention v2 (causal), 3-stage KV, 1 barrier/iter ---
// CTA: 128 q-rows, 8 warps x 16 rows.  KV tiles: 64 wide, TRIPLE buffered.
// Heavy-first scheduling: qtb = gridDim.x-1-blockIdx.x (long CTAs start first).
#define QLD 136
#define KLD 136
#define VLD 72
#define KSTG (64 * KLD)                          // halfs per K stage
#define VSTG (128 * VLD)                         // halfs per Vt stage
#define FA2_SQ   (128 * QLD * 2)                 // 34816
#define FA2_SMEM (FA2_SQ + 3 * (KSTG + VSTG) * 2)  // 142336

__global__ __launch_bounds__(256, 1) void k_flash2() {
    extern __shared__ char smem[];
    __half* sQ = (__half*)smem;
    __half* sK = sQ + 128 * QLD;                 // [3][64][KLD]
    __half* sVt = sK + 3 * KSTG;                 // [3][128][VLD]

    const int qtb = gridDim.x - 1 - blockIdx.x;  // heavy-first
    const int h = blockIdx.y, b = blockIdx.z;
    const int q0 = qtb * 128;
    const int tid = threadIdx.x, warp = tid >> 5, lane = tid & 31;
    const int l4 = lane >> 2, lq = lane & 3;
    const int wr = warp * 16;                      // warp's local q-row base
    const size_t headQK = ((size_t)(b * NH + h)) * S_ * HD;
    const size_t headVt = ((size_t)(b * NH + h)) * HD * S_;
    const float NEG_INF = __int_as_float(0xff800000);

    const int ktmax = 2 * qtb + 1;                 // inclusive

    auto issueKV = [&](int kt, int buf) {
        const int k0 = kt * 64;
        __half* dK = sK + buf * KSTG;
        __half* dV = sVt + buf * VSTG;
#pragma unroll
        for (int i = 0; i < 4; i++) {              // K: 64 rows x 16 chunks
            int ch = tid + i * 256;
            int r = ch >> 4, c = (ch & 15) << 3;
            cpa16(dK + r * KLD + c, g_kh + headQK + (size_t)(k0 + r) * HD + c);
        }
#pragma unroll
        for (int i = 0; i < 4; i++) {              // Vt: 128 rows x 8 chunks
            int ch = tid + i * 256;
            int r = ch >> 3, c = (ch & 7) << 3;
            cpa16(dV + r * VLD + c, g_vt + headVt + (size_t)r * S_ + k0 + c);
        }
        cpa_commit();
    };

    // prologue: Q group, then KV(0), KV(1)
#pragma unroll
    for (int i = 0; i < 8; i++) {                  // Q: 128 rows x 16 chunks
        int ch = tid + i * 256;
        int r = ch >> 4, c = (ch & 15) << 3;
        cpa16(sQ + r * QLD + c, g_qh + headQK + (size_t)(q0 + r) * HD + c);
    }
    cpa_commit();
    issueKV(0, 0);
    issueKV(1, 1);                                 // ktmax >= 1 always
    cpa_wait2();                                   // Q retired (KV0,KV1 may pend)
    __syncthreads();

    // preload Q A-fragments: 8 k-blocks x 4 regs
    unsigned qa[8][4];
    {
        const __half* q0p = sQ + (wr + l4) * QLD;
        const __half* q1p = q0p + 8 * QLD;
#pragma unroll
        for (int kb = 0; kb < 8; kb++) {
            qa[kb][0] = *(const unsigned*)&q0p[kb * 16 + 2 * lq];
            qa[kb][1] = *(const unsigned*)&q1p[kb * 16 + 2 * lq];
            qa[kb][2] = *(const unsigned*)&q0p[kb * 16 + 2 * lq + 8];
            qa[kb][3] = *(const unsigned*)&q1p[kb * 16 + 2 * lq + 8];
        }
    }

    float oacc[16][4];
#pragma unroll
    for (int t = 0; t < 16; t++)
#pragma unroll
        for (int e = 0; e < 4; e++) oacc[t][e] = 0.0f;
    float m0 = -1e30f, m1 = -1e30f, l0 = 0.0f, l1 = 0.0f;

    const int qrow0 = q0 + wr + l4;                // global rows of this thread
    const int qrow1 = qrow0 + 8;

    for (int kt = 0; kt <= ktmax; kt++) {
        const int cur = kt % 3;
        const int k0 = kt * 64;
        if (kt + 1 <= ktmax) cpa_wait1();          // KV(kt) retired; KV(kt+1) pends
        else                 cpa_wait0();
        __syncthreads();                           // KV(kt) visible; stage (kt+2)%3 free
        if (kt + 2 <= ktmax) issueKV(kt + 2, (kt + 2) % 3);

        const bool active = (k0 <= q0 + wr + 15);
        if (active) {
            const __half* pK = sK + cur * KSTG;
            const __half* pVt = sVt + cur * VSTG;

            // ---- S = Q K^T : 8 n-tiles (8 kv each) ----
            float sacc[8][4];
#pragma unroll
            for (int n = 0; n < 8; n++) {
#pragma unroll
                for (int e = 0; e < 4; e++) sacc[n][e] = 0.0f;
                const __half* kp = pK + (n * 8 + l4) * KLD;
#pragma unroll
                for (int kb = 0; kb < 8; kb++) {
                    unsigned bb[2];
                    bb[0] = *(const unsigned*)&kp[kb * 16 + 2 * lq];
                    bb[1] = *(const unsigned*)&kp[kb * 16 + 2 * lq + 8];
                    mma16816(sacc[n], qa[kb], bb, sacc[n]);
                }
            }

            // ---- causal mask ----
            if (k0 + 63 > q0 + wr) {
#pragma unroll
                for (int n = 0; n < 8; n++) {
                    int c0 = k0 + n * 8 + 2 * lq;
                    if (c0 > qrow0)     sacc[n][0] = NEG_INF;
                    if (c0 + 1 > qrow0) sacc[n][1] = NEG_INF;
                    if (c0 > qrow1)     sacc[n][2] = NEG_INF;
                    if (c0 + 1 > qrow1) sacc[n][3] = NEG_INF;
                }
            }

            // ---- online softmax in registers ----
            float mx0 = NEG_INF, mx1 = NEG_INF;
#pragma unroll
            for (int n = 0; n < 8; n++) {
                mx0 = fmaxf(mx0, fmaxf(sacc[n][0], sacc[n][1]));
                mx1 = fmaxf(mx1, fmaxf(sacc[n][2], sacc[n][3]));
            }
            mx0 = fmaxf(mx0, __shfl_xor_sync(0xffffffffu, mx0, 1));
            mx0 = fmaxf(mx0, __shfl_xor_sync(0xffffffffu, mx0, 2));
            mx1 = fmaxf(mx1, __shfl_xor_sync(0xffffffffu, mx1, 1));
            mx1 = fmaxf(mx1, __shfl_xor_sync(0xffffffffu, mx1, 2));
            float m0n = fmaxf(m0, mx0);
            float m1n = fmaxf(m1, mx1);
            float sum0 = 0.f, sum1 = 0.f;
#pragma unroll
            for (int n = 0; n < 8; n++) {
                sacc[n][0] = __expf(sacc[n][0] - m0n);
                sacc[n][1] = __expf(sacc[n][1] - m0n);
                sacc[n][2] = __expf(sacc[n][2] - m1n);
                sacc[n][3] = __expf(sacc[n][3] - m1n);
                sum0 += sacc[n][0] + sacc[n][1];
                sum1 += sacc[n][2] + sacc[n][3];
            }
            sum0 += __shfl_xor_sync(0xffffffffu, sum0, 1);
            sum0 += __shfl_xor_sync(0xffffffffu, sum0, 2);
            sum1 += __shfl_xor_sync(0xffffffffu, sum1, 1);
            sum1 += __shfl_xor_sync(0xffffffffu, sum1, 2);
            float al0 = __expf(m0 - m0n);
            float al1 = __expf(m1 - m1n);
            m0 = m0n; m1 = m1n;
            l0 = l0 * al0 + sum0;
            l1 = l1 * al1 + sum1;

            // ---- pack P (fp16 A-fragments) ----
            unsigned pa[4][4];
#pragma unroll
            for (int j = 0; j < 4; j++) {
                __half2 h0 = __floats2half2_rn(sacc[2 * j][0], sacc[2 * j][1]);
                __half2 h1 = __floats2half2_rn(sacc[2 * j][2], sacc[2 * j][3]);
                __half2 h2 = __floats2half2_rn(sacc[2 * j + 1][0], sacc[2 * j + 1][1]);
                __half2 h3 = __floats2half2_rn(sacc[2 * j + 1][2], sacc[2 * j + 1][3]);
                pa[j][0] = *(unsigned*)&h0;
                pa[j][1] = *(unsigned*)&h1;
                pa[j][2] = *(unsigned*)&h2;
                pa[j][3] = *(unsigned*)&h3;
            }

            // ---- rescale O, then O += P * Vt ----
#pragma unroll
            for (int t = 0; t < 16; t++) {
                oacc[t][0] *= al0; oacc[t][1] *= al0;
                oacc[t][2] *= al1; oacc[t][3] *= al1;
            }
#pragma unroll
            for (int t = 0; t < 16; t++) {
                const __half* vp = pVt + (t * 8 + l4) * VLD;
#pragma unroll
                for (int j = 0; j < 4; j++) {
                    unsigned bb[2];
                    bb[0] = *(const unsigned*)&vp[j * 16 + 2 * lq];
                    bb[1] = *(const unsigned*)&vp[j * 16 + 2 * lq + 8];
                    mma16816(oacc[t], pa[j], bb, oacc[t]);
                }
            }
        }
    }

    // ---- epilogue: O / l -> stage in sQ (half, warp-private rows) ----
    {
        float inv0 = 1.0f / l0, inv1 = 1.0f / l1;
        __half* st0 = sQ + (wr + l4) * QLD;
        __half* st1 = st0 + 8 * QLD;
#pragma unroll
        for (int t = 0; t < 16; t++) {
            __half2 h0 = __floats2half2_rn(oacc[t][0] * inv0, oacc[t][1] * inv0);
            __half2 h1 = __floats2half2_rn(oacc[t][2] * inv1, oacc[t][3] * inv1);
            *(__half2*)&st0[t * 8 + 2 * lq] = h0;
            *(__half2*)&st1[t * 8 + 2 * lq] = h1;
        }
    }
    __syncthreads();                               // staging visible to all warps
#pragma unroll
    for (int i = 0; i < 8; i++) {
        int ch = tid + i * 256;
        int r = ch >> 4, c = (ch & 15) << 3;
        *(uint4*)&g_yh[((size_t)(b * S_ + q0 + r)) * H_ + h * HD + c] =
            *(const uint4*)&sQ[r * QLD + c];
    }
}

// ---------------- launch -----------------------------------------------------
extern "C" void kernel_launch(void* const* d_in, const int* in_sizes, int n_in,
                              void* d_out, int out_size) {
    (void)in_sizes; (void)n_in; (void)out_size;
    const float* x      = (const float*)d_in[0];
    const float* rotary = (const float*)d_in[1];
    const float* qkvw   = (const float*)d_in[2];
    const float* ow     = (const float*)d_in[3];
    float* out = (float*)d_out;

    static int attr_set = 0;
    if (!attr_set) {
        cudaFuncSetAttribute(k_gemm, cudaFuncAttributeMaxDynamicSharedMemorySize, GSM_TOTAL);
        cudaFuncSetAttribute(k_flash2, cudaFuncAttributeMaxDynamicSharedMemorySize, FA2_SMEM);
        attr_set = 1;
    }

    // 1) deterministic scales (both weights in one launch)
    k_abs_partial<<<dim3(512, 2), 256>>>(qkvw, ow);
    k_finalize_scales<<<1, 256>>>();

    // 2) quantize both weights + x->half in ONE launch
    k_convert<<<dim3(2048, 3), 256>>>(qkvw, ow, x);

    // 3) QKV projection + fused RoPE/transpose epilogue (V transposed)
    k_gemm<<<dim3(QKV_N / 128, BS / 128), 256, GSM_TOTAL>>>(nullptr, rotary, BS, QKV_N, H_, 0);

    // 4) flash attention v2 (causal, register-resident, 3-stage KV, heavy-first)
    k_flash2<<<dim3(S_ / 128, NH, B_), 256, FA2_SMEM>>>();

    // 5) output projection -> d_out (fp32)
    k_gemm<<<dim3(H_ / 128, BS / 128), 256, GSM_TOTAL>>>(out, nullptr, BS, H_, H_, 1);
}